// round 1
// baseline (speedup 1.0000x reference)
#include <cuda_runtime.h>

#define DIM 1024
#define NROWS 32        // B*T = 2*16 distinct kv rows
#define TPF 1560        // tokens per frame
#define KCH 256         // K-chunk held in smem per pass
#define LDS_PITCH (KCH + 1)

// Scratch (no cudaMalloc allowed): intermediate v and final per-frame y.
__device__ float g_v[NROWS * DIM];
__device__ float g_y[NROWS * DIM];

// OUT[r, col] = sum_k IN[r, k] * W[col, k] + bias[col]
// IN is [32, 1024]; W is [1024, 1024] row-major (so this computes IN @ W^T + b).
// Layout: lane = row (32 rows == 32 lanes), warp = one output column,
// grid.x * 8 warps cover all 1024 columns. c-chunk lives in smem with a
// pitch of 257 floats so lanes (stride 257 ≡ 1 mod 32) are conflict-free.
__global__ __launch_bounds__(256) void gemm32_kernel(
    const float* __restrict__ in,
    const float* __restrict__ W,
    const float* __restrict__ bias,
    float* __restrict__ out)
{
    __shared__ float s[NROWS * LDS_PITCH];   // 32 * 257 * 4 = 32,896 B

    const int tid  = threadIdx.x;
    const int lane = tid & 31;
    const int warp = tid >> 5;
    const int col  = blockIdx.x * 8 + warp;

    float acc = 0.0f;

    for (int kc = 0; kc < DIM; kc += KCH) {
        __syncthreads();
        // Fill smem: coalesced global reads, conflict-free smem writes.
        #pragma unroll
        for (int i = tid; i < NROWS * KCH; i += 256) {
            int r = i >> 8;            // KCH == 256
            int k = i & (KCH - 1);
            s[r * LDS_PITCH + k] = in[r * DIM + kc + k];
        }
        __syncthreads();

        const float* Wp = W + (size_t)col * DIM + kc;
        const float* sp = s + lane * LDS_PITCH;
        #pragma unroll 8
        for (int k = 0; k < KCH; k += 4) {
            float4 w4 = *reinterpret_cast<const float4*>(Wp + k);
            acc += sp[k + 0] * w4.x;
            acc += sp[k + 1] * w4.y;
            acc += sp[k + 2] * w4.z;
            acc += sp[k + 3] * w4.w;
        }
    }

    out[lane * DIM + col] = acc + bias[col];
}

// Broadcast y[frame, :] (1024 fp32 = 256 float4) to all 1560 rows of that frame.
// gridDim.x * blockDim.x is a multiple of 256, so (global_idx & 255) == tid:
// each thread's source value is LOOP-INVARIANT -> load once, then a pure
// coalesced STG.128 stream (DRAM-write-bound, the true floor of this problem).
__global__ __launch_bounds__(256) void bcast_kernel(
    const float4* __restrict__ y4,
    float4* __restrict__ out4)
{
    const int f   = blockIdx.y;                  // frame 0..31
    const int tid = threadIdx.x;
    const float4 val = y4[f * 256 + tid];

    const int per_frame = TPF * 256;             // 399,360 float4 per frame
    const long base = (long)f * per_frame;
    const int stride = gridDim.x * 256;

    for (int i = blockIdx.x * 256 + tid; i < per_frame; i += stride) {
        out4[base + i] = val;
    }
}

extern "C" void kernel_launch(void* const* d_in, const int* in_sizes, int n_in,
                              void* d_out, int out_size)
{
    // metadata order: x, c, Wq, bq, Wk, bk, Wv, bv, Wo, bo
    // softmax over a length-1 kv axis is identically 1 -> x/Wq/bq/Wk/bk unused.
    const float* c  = (const float*)d_in[1];
    const float* Wv = (const float*)d_in[6];
    const float* bv = (const float*)d_in[7];
    const float* Wo = (const float*)d_in[8];
    const float* bo = (const float*)d_in[9];
    float* out = (float*)d_out;

    void* vptr = nullptr;
    void* yptr = nullptr;
    cudaGetSymbolAddress(&vptr, g_v);
    cudaGetSymbolAddress(&yptr, g_y);
    float* v = (float*)vptr;
    float* y = (float*)yptr;

    // v = c @ Wv^T + bv        (32 x 1024)
    gemm32_kernel<<<128, 256>>>(c, Wv, bv, v);
    // y = v @ Wo^T + bo        (32 x 1024)
    gemm32_kernel<<<128, 256>>>(v, Wo, bo, y);
    // out[b, t*1560+i, :] = y[b,t,:]   (204 MB broadcast store)
    bcast_kernel<<<dim3(40, 32), 256>>>((const float4*)y, (float4*)out);

    (void)in_sizes; (void)n_in; (void)out_size;
}

// round 2
// speedup vs baseline: 1.8349x; 1.8349x over previous
#include <cuda_runtime.h>

#define DIM 1024
#define NROWS 32        // B*T = 2*16 distinct kv rows
#define TPF 1560        // tokens per frame

// Scratch (no cudaMalloc allowed): intermediate v and final per-frame y.
__device__ float g_v[NROWS * DIM];
__device__ float g_y[NROWS * DIM];

// OUT[r, col] = sum_k IN[r, k] * W[col, k] + bias[col]
// IN: [32, 1024], W: [1024, 1024] row-major  (=> IN @ W^T + b)
//
// Decomposition: one warp per output column; K split across lanes
// (lane l covers k = i*128 + 4l .. 4l+3 for i in 0..7). The 8 W float4
// loads per warp are coalesced 512B LDG.128s, ALL issued before the smem
// staging loop -> full-W MLP, DRAM-bandwidth-bound instead of latency-bound.
// Input matrix (128 KB) staged once per block in dynamic smem.
// Butterfly-shuffle reduces acc[32] across lanes; lane r writes row r.
__global__ __launch_bounds__(256) void gemm32_kernel(
    const float* __restrict__ in,
    const float* __restrict__ W,
    const float* __restrict__ bias,
    float* __restrict__ out)
{
    extern __shared__ float s[];                 // 32*1024 floats = 128 KB

    const int tid  = threadIdx.x;
    const int lane = tid & 31;
    const int warp = tid >> 5;
    const int col  = blockIdx.x * 8 + warp;

    // 1) Issue all 8 coalesced W loads up front (independent of staging).
    const float4* Wp4 = reinterpret_cast<const float4*>(W + (size_t)col * DIM);
    float4 w[8];
    #pragma unroll
    for (int i = 0; i < 8; i++) w[i] = Wp4[i * 32 + lane];

    // 2) Stage the full input matrix into smem (L2-resident after 1st block).
    const float4* in4 = reinterpret_cast<const float4*>(in);
    float4* s4 = reinterpret_cast<float4*>(s);
    #pragma unroll
    for (int i = tid; i < NROWS * DIM / 4; i += 256) s4[i] = in4[i];
    __syncthreads();

    // 3) Accumulate: per lane, 32 rows x its K-slice.
    float acc[NROWS];
    #pragma unroll
    for (int r = 0; r < NROWS; r++) acc[r] = 0.0f;

    #pragma unroll
    for (int i = 0; i < 8; i++) {
        const int k = i * 128 + lane * 4;
        #pragma unroll
        for (int r = 0; r < NROWS; r++) {
            float4 x = *reinterpret_cast<const float4*>(s + r * DIM + k);
            acc[r] += x.x * w[i].x + x.y * w[i].y + x.z * w[i].z + x.w * w[i].w;
        }
    }

    // 4) Butterfly reduction across lanes (all lanes end with all row sums).
    #pragma unroll
    for (int off = 16; off; off >>= 1)
        #pragma unroll
        for (int r = 0; r < NROWS; r++)
            acc[r] += __shfl_xor_sync(0xffffffffu, acc[r], off);

    // Lane r writes row r (compile-time-indexed select avoids local spill).
    float res = 0.0f;
    #pragma unroll
    for (int r = 0; r < NROWS; r++) if (lane == r) res = acc[r];

    out[lane * DIM + col] = res + bias[col];
}

// Broadcast y[frame, :] (1024 fp32 = 256 float4) to all 1560 rows of the frame.
// Each thread's source value is loop-invariant -> pure coalesced STG.128 stream.
__global__ __launch_bounds__(256) void bcast_kernel(
    const float4* __restrict__ y4,
    float4* __restrict__ out4)
{
    const int f   = blockIdx.y;                  // frame 0..31
    const int tid = threadIdx.x;
    const float4 val = y4[f * 256 + tid];

    const int per_frame = TPF * 256;             // 399,360 float4 per frame
    const long base = (long)f * per_frame;
    const int stride = gridDim.x * 256;

    for (int i = blockIdx.x * 256 + tid; i < per_frame; i += stride) {
        out4[base + i] = val;
    }
}

extern "C" void kernel_launch(void* const* d_in, const int* in_sizes, int n_in,
                              void* d_out, int out_size)
{
    // metadata order: x, c, Wq, bq, Wk, bk, Wv, bv, Wo, bo
    // softmax over a length-1 kv axis is identically 1 -> x/Wq/bq/Wk/bk unused.
    const float* c  = (const float*)d_in[1];
    const float* Wv = (const float*)d_in[6];
    const float* bv = (const float*)d_in[7];
    const float* Wo = (const float*)d_in[8];
    const float* bo = (const float*)d_in[9];
    float* out = (float*)d_out;

    void* vptr = nullptr;
    void* yptr = nullptr;
    cudaGetSymbolAddress(&vptr, g_v);
    cudaGetSymbolAddress(&yptr, g_y);
    float* v = (float*)vptr;
    float* y = (float*)yptr;

    const int smem_bytes = NROWS * DIM * sizeof(float);   // 128 KB
    cudaFuncSetAttribute(gemm32_kernel,
                         cudaFuncAttributeMaxDynamicSharedMemorySize, smem_bytes);

    // v = c @ Wv^T + bv        (32 x 1024)
    gemm32_kernel<<<128, 256, smem_bytes>>>(c, Wv, bv, v);
    // y = v @ Wo^T + bo        (32 x 1024)
    gemm32_kernel<<<128, 256, smem_bytes>>>(v, Wo, bo, y);
    // out[b, t*1560+i, :] = y[b,t,:]   (204 MB broadcast store)
    bcast_kernel<<<dim3(40, 32), 256>>>((const float4*)y, (float4*)out);

    (void)in_sizes; (void)n_in; (void)out_size;
}

// round 3
// speedup vs baseline: 2.1653x; 1.1801x over previous
#include <cuda_runtime.h>

#define DIM 1024
#define NROWS 32        // B*T = 2*16 distinct kv rows
#define TPF 1560        // tokens per frame

// Scratch (no cudaMalloc allowed): intermediate v and final per-frame y.
__device__ float g_v[NROWS * DIM];
__device__ float g_y[NROWS * DIM];

// OUT[r, col] = sum_k IN[r, k] * W[col, k] + bias[col]
// IN: [32, 1024], W: [1024, 1024] row-major  (=> IN @ W^T + b)
//
// Warp tile: 8 rows x 4 cols (acc[8][4]); K split across lanes as float4
// (chunk = 128 k, lane l covers k = ch*128 + 4l). Per chunk: 4 coalesced
// W LDG.128 + 8 x LDG.128 feed 128 FFMAs. Next chunk's loads are
// double-buffered so DRAM latency hides behind FFMA issue. No smem: the
// 128 KB input matrix is L1/L2-resident and each block re-reads it 8x.
// Block = 8 warps = 4 row-groups x 2 col-groups -> covers 32 rows x 8 cols.
// Grid = 128 blocks covers all 1024 columns.
__global__ __launch_bounds__(256) void gemm32_kernel(
    const float* __restrict__ in,
    const float* __restrict__ W,
    const float* __restrict__ bias,
    float* __restrict__ out)
{
    const int tid  = threadIdx.x;
    const int lane = tid & 31;
    const int warp = tid >> 5;
    const int rg   = warp & 3;              // row group: rows rg*8 .. rg*8+7
    const int cg   = warp >> 2;             // col group within block (0..1)
    const int row0 = rg * 8;
    const int col0 = blockIdx.x * 8 + cg * 4;

    const float4* W4  = reinterpret_cast<const float4*>(W);
    const float4* in4 = reinterpret_cast<const float4*>(in);

    float4 wb[2][4], xb[2][8];
    float acc[8][4];
    #pragma unroll
    for (int r = 0; r < 8; r++)
        #pragma unroll
        for (int c = 0; c < 4; c++) acc[r][c] = 0.0f;

    // prefetch chunk 0
    {
        const int koff = lane;              // ch*32 + lane, ch=0
        #pragma unroll
        for (int c = 0; c < 4; c++)
            wb[0][c] = __ldg(&W4[(size_t)(col0 + c) * 256 + koff]);
        #pragma unroll
        for (int r = 0; r < 8; r++)
            xb[0][r] = __ldg(&in4[(row0 + r) * 256 + koff]);
    }

    #pragma unroll
    for (int ch = 0; ch < 8; ch++) {
        const int cur = ch & 1;
        if (ch < 7) {
            const int nxt  = cur ^ 1;
            const int koff = (ch + 1) * 32 + lane;
            #pragma unroll
            for (int c = 0; c < 4; c++)
                wb[nxt][c] = __ldg(&W4[(size_t)(col0 + c) * 256 + koff]);
            #pragma unroll
            for (int r = 0; r < 8; r++)
                xb[nxt][r] = __ldg(&in4[(row0 + r) * 256 + koff]);
        }
        #pragma unroll
        for (int r = 0; r < 8; r++) {
            float4 x = xb[cur][r];
            #pragma unroll
            for (int c = 0; c < 4; c++) {
                float4 w = wb[cur][c];
                acc[r][c] += x.x * w.x + x.y * w.y + x.z * w.z + x.w * w.w;
            }
        }
    }

    // Butterfly-reduce each of the 32 accumulators across lanes.
    #pragma unroll
    for (int off = 16; off; off >>= 1)
        #pragma unroll
        for (int r = 0; r < 8; r++)
            #pragma unroll
            for (int c = 0; c < 4; c++)
                acc[r][c] += __shfl_xor_sync(0xffffffffu, acc[r][c], off);

    // Lane (r*4 + c) writes element (row0+r, col0+c).
    float res = 0.0f;
    #pragma unroll
    for (int r = 0; r < 8; r++)
        #pragma unroll
        for (int c = 0; c < 4; c++)
            if (lane == r * 4 + c) res = acc[r][c];

    const int r = lane >> 2, c = lane & 3;
    out[(row0 + r) * DIM + col0 + c] = res + bias[col0 + c];
}

// Broadcast y[frame, :] (1024 fp32 = 256 float4) to all 1560 rows of the frame.
// Source value is loop-invariant per thread -> pure coalesced streaming stores.
__global__ __launch_bounds__(256) void bcast_kernel(
    const float4* __restrict__ y4,
    float4* __restrict__ out4)
{
    const int f   = blockIdx.y;                  // frame 0..31
    const int tid = threadIdx.x;
    const float4 val = y4[f * 256 + tid];

    const int per_frame = TPF * 256;             // 399,360 float4 per frame
    const long base = (long)f * per_frame;
    const int stride = gridDim.x * 256;

    for (int i = blockIdx.x * 256 + tid; i < per_frame; i += stride) {
        __stcs(&out4[base + i], val);            // streaming store: don't churn L2
    }
}

extern "C" void kernel_launch(void* const* d_in, const int* in_sizes, int n_in,
                              void* d_out, int out_size)
{
    // metadata order: x, c, Wq, bq, Wk, bk, Wv, bv, Wo, bo
    // softmax over a length-1 kv axis is identically 1 -> x/Wq/bq/Wk/bk unused.
    const float* c  = (const float*)d_in[1];
    const float* Wv = (const float*)d_in[6];
    const float* bv = (const float*)d_in[7];
    const float* Wo = (const float*)d_in[8];
    const float* bo = (const float*)d_in[9];
    float* out = (float*)d_out;

    void* vptr = nullptr;
    void* yptr = nullptr;
    cudaGetSymbolAddress(&vptr, g_v);
    cudaGetSymbolAddress(&yptr, g_y);
    float* v = (float*)vptr;
    float* y = (float*)yptr;

    // v = c @ Wv^T + bv        (32 x 1024)
    gemm32_kernel<<<128, 256>>>(c, Wv, bv, v);
    // y = v @ Wo^T + bo        (32 x 1024)
    gemm32_kernel<<<128, 256>>>(v, Wo, bo, y);
    // out[b, t*1560+i, :] = y[b,t,:]   (204 MB broadcast store)
    bcast_kernel<<<dim3(65, 32), 256>>>((const float4*)y, (float4*)out);

    (void)in_sizes; (void)n_in; (void)out_size;
}

// round 4
// speedup vs baseline: 2.3709x; 1.0949x over previous
#include <cuda_runtime.h>

#define DIM 1024
#define NROWS 32        // B*T = 2*16 distinct kv rows
#define TPF 1560        // tokens per frame

// Scratch (no cudaMalloc allowed): intermediate v and final per-frame y.
__device__ float g_v[NROWS * DIM];
__device__ float g_y[NROWS * DIM];

// OUT[r, col] = sum_k IN[r, k] * W[col, k] + bias[col]
// IN: [32, 1024], W: [1024, 1024] row-major  (=> IN @ W^T + b)
//
// Warp tile: 4 rows x 4 cols (acc[16] -- small enough that the double
// buffers fit in registers WITHOUT spilling: 16 acc + 32 wb + 32 xb = 80).
// K split across lanes as float4 (chunk = 128 k). Per chunk: 8 coalesced
// LDG.128 feed 64 FFMAs, next chunk double-buffered.
// Block = 8 warps = 4 row-groups x 2 col-groups = 16 rows x 8 cols.
// Grid = 256 blocks (128 col-blocks x 2 row-blocks): ~1.7 CTA/SM so
// latency is hidden by occupancy, not just the 1-deep prefetch.
__global__ __launch_bounds__(256, 2) void gemm32_kernel(
    const float* __restrict__ in,
    const float* __restrict__ W,
    const float* __restrict__ bias,
    float* __restrict__ out)
{
    const int tid  = threadIdx.x;
    const int lane = tid & 31;
    const int warp = tid >> 5;
    const int rg   = warp & 3;               // row group within block
    const int cg   = warp >> 2;              // col group within block (0..1)
    const int cb   = blockIdx.x & 127;       // col block (8 cols each)
    const int rb   = blockIdx.x >> 7;        // row block (16 rows each)
    const int row0 = rb * 16 + rg * 4;
    const int col0 = cb * 8 + cg * 4;

    const float4* W4  = reinterpret_cast<const float4*>(W);
    const float4* in4 = reinterpret_cast<const float4*>(in);

    float4 wb[2][4], xb[2][4];
    float acc[4][4];
    #pragma unroll
    for (int r = 0; r < 4; r++)
        #pragma unroll
        for (int c = 0; c < 4; c++) acc[r][c] = 0.0f;

    // prefetch chunk 0
    #pragma unroll
    for (int c = 0; c < 4; c++)
        wb[0][c] = __ldg(&W4[(size_t)(col0 + c) * 256 + lane]);
    #pragma unroll
    for (int r = 0; r < 4; r++)
        xb[0][r] = __ldg(&in4[(row0 + r) * 256 + lane]);

    #pragma unroll
    for (int ch = 0; ch < 8; ch++) {
        const int cur = ch & 1;
        if (ch < 7) {
            const int nxt  = cur ^ 1;
            const int koff = (ch + 1) * 32 + lane;
            #pragma unroll
            for (int c = 0; c < 4; c++)
                wb[nxt][c] = __ldg(&W4[(size_t)(col0 + c) * 256 + koff]);
            #pragma unroll
            for (int r = 0; r < 4; r++)
                xb[nxt][r] = __ldg(&in4[(row0 + r) * 256 + koff]);
        }
        #pragma unroll
        for (int r = 0; r < 4; r++) {
            float4 x = xb[cur][r];
            #pragma unroll
            for (int c = 0; c < 4; c++) {
                float4 w = wb[cur][c];
                acc[r][c] += x.x * w.x + x.y * w.y + x.z * w.z + x.w * w.w;
            }
        }
    }

    // Butterfly-reduce the 16 accumulators across lanes.
    #pragma unroll
    for (int off = 16; off; off >>= 1)
        #pragma unroll
        for (int r = 0; r < 4; r++)
            #pragma unroll
            for (int c = 0; c < 4; c++)
                acc[r][c] += __shfl_xor_sync(0xffffffffu, acc[r][c], off);

    // Lane (r*4 + c), lanes 0..15, writes element (row0+r, col0+c).
    float res = 0.0f;
    #pragma unroll
    for (int r = 0; r < 4; r++)
        #pragma unroll
        for (int c = 0; c < 4; c++)
            if (lane == r * 4 + c) res = acc[r][c];

    if (lane < 16) {
        const int r = lane >> 2, c = lane & 3;
        out[(row0 + r) * DIM + col0 + c] = res + bias[col0 + c];
    }
}

// Broadcast y[frame, :] (1024 fp32 = 256 float4) to all 1560 rows of the frame.
// Source value is loop-invariant per thread -> pure coalesced streaming stores.
__global__ __launch_bounds__(256) void bcast_kernel(
    const float4* __restrict__ y4,
    float4* __restrict__ out4)
{
    const int f   = blockIdx.y;                  // frame 0..31
    const int tid = threadIdx.x;
    const float4 val = y4[f * 256 + tid];

    const int per_frame = TPF * 256;             // 399,360 float4 per frame
    const long base = (long)f * per_frame;
    const int stride = gridDim.x * 256;

    for (int i = blockIdx.x * 256 + tid; i < per_frame; i += stride) {
        __stcs(&out4[base + i], val);            // streaming store: don't churn L2
    }
}

extern "C" void kernel_launch(void* const* d_in, const int* in_sizes, int n_in,
                              void* d_out, int out_size)
{
    // metadata order: x, c, Wq, bq, Wk, bk, Wv, bv, Wo, bo
    // softmax over a length-1 kv axis is identically 1 -> x/Wq/bq/Wk/bk unused.
    const float* c  = (const float*)d_in[1];
    const float* Wv = (const float*)d_in[6];
    const float* bv = (const float*)d_in[7];
    const float* Wo = (const float*)d_in[8];
    const float* bo = (const float*)d_in[9];
    float* out = (float*)d_out;

    void* vptr = nullptr;
    void* yptr = nullptr;
    cudaGetSymbolAddress(&vptr, g_v);
    cudaGetSymbolAddress(&yptr, g_y);
    float* v = (float*)vptr;
    float* y = (float*)yptr;

    // v = c @ Wv^T + bv        (32 x 1024)
    gemm32_kernel<<<256, 256>>>(c, Wv, bv, v);
    // y = v @ Wo^T + bo        (32 x 1024)
    gemm32_kernel<<<256, 256>>>(v, Wo, bo, y);
    // out[b, t*1560+i, :] = y[b,t,:]   (204 MB broadcast store)
    bcast_kernel<<<dim3(65, 32), 256>>>((const float4*)y, (float4*)out);

    (void)in_sizes; (void)n_in; (void)out_size;
}